// round 15
// baseline (speedup 1.0000x reference)
#include <cuda_runtime.h>
#include <cuda_bf16.h>
#include <cstdint>

#define Bc 4
#define Tt 1024
#define Dd 512
#define Cc 8
#define Hh 8

// ---------------- scratch (device globals) ---------------------------------
__device__ int   g_assign[Bc * Tt];
__device__ int   g_counts[Bc * Cc];
__device__ int   g_list[Bc * Tt];
#define PLN (Bc * Hh * Tt * 64)
__device__ __nv_bfloat16 g_Qhi[PLN], g_Qlo[PLN];
__device__ __nv_bfloat16 g_Khi[PLN], g_Klo[PLN];
__device__ __nv_bfloat16 g_Vhi[PLN], g_Vlo[PLN];
__device__ __nv_bfloat16 g_Chi[Bc * Tt * Dd], g_Clo[Bc * Tt * Dd];

static __device__ __forceinline__ uint32_t s2u(const void* p) {
    uint32_t a;
    asm("{ .reg .u64 t; cvta.to.shared.u64 t, %1; cvt.u32.u64 %0, t; }" : "=r"(a) : "l"(p));
    return a;
}
#define LDSM4(r0, r1, r2, r3, addr) \
    asm volatile("ldmatrix.sync.aligned.m8n8.x4.shared.b16 {%0,%1,%2,%3}, [%4];" \
                 : "=r"(r0), "=r"(r1), "=r"(r2), "=r"(r3) : "r"(addr))
#define LDSM4T(r0, r1, r2, r3, addr) \
    asm volatile("ldmatrix.sync.aligned.m8n8.x4.trans.shared.b16 {%0,%1,%2,%3}, [%4];" \
                 : "=r"(r0), "=r"(r1), "=r"(r2), "=r"(r3) : "r"(addr))
#define MMA16816(d, a, b0, b1) \
    asm volatile("mma.sync.aligned.m16n8k16.row.col.f32.bf16.bf16.f32 " \
                 "{%0,%1,%2,%3}, {%4,%5,%6,%7}, {%8,%9}, {%0,%1,%2,%3};" \
                 : "+f"((d)[0]), "+f"((d)[1]), "+f"((d)[2]), "+f"((d)[3]) \
                 : "r"((a)[0]), "r"((a)[1]), "r"((a)[2]), "r"((a)[3]), \
                   "r"((b0)), "r"((b1)))

static __device__ __forceinline__ uint32_t packbf(float x, float y) {
    __nv_bfloat162 t = __halves2bfloat162(__float2bfloat16(x), __float2bfloat16(y));
    return *(uint32_t*)&t;
}

// ---------------- 1) cluster argmax (fp32 Kahan) ---------------------------
__global__ void k_assign(const float* __restrict__ X,
                         const float* __restrict__ Wc,
                         const float* __restrict__ bc) {
    int gw   = (blockIdx.x * blockDim.x + threadIdx.x) >> 5;
    int lane = threadIdx.x & 31;
    if (gw >= Bc * Tt) return;
    const float4* x4 = (const float4*)(X + (size_t)gw * Dd);
    float4 xr[4];
#pragma unroll
    for (int r = 0; r < 4; r++) xr[r] = x4[lane + (r << 5)];
    float best = -1e30f; int bi = 0;
#pragma unroll
    for (int c = 0; c < Cc; c++) {
        const float4* w4 = (const float4*)(Wc + c * Dd);
        float sum = 0.f, comp = 0.f;
#pragma unroll
        for (int r = 0; r < 4; r++) {
            float4 w = w4[lane + (r << 5)];
            float pr[4] = {xr[r].x * w.x, xr[r].y * w.y, xr[r].z * w.z, xr[r].w * w.w};
#pragma unroll
            for (int q = 0; q < 4; q++) {
                float y = pr[q] - comp;
                float t = sum + y;
                comp = (t - sum) - y;
                sum = t;
            }
        }
#pragma unroll
        for (int o = 16; o; o >>= 1) sum += __shfl_xor_sync(0xffffffffu, sum, o);
        float s = sum + bc[c];
        if (s > best) { best = s; bi = c; }
    }
    if (lane == 0) g_assign[gw] = bi;
}

// ---------------- 2) stable per-cluster rank via ballots -------------------
__global__ void __launch_bounds__(1024) k_rank() {
    __shared__ int warp_hist[32][8];
    __shared__ int tot[8];
    int b = blockIdx.x, t = threadIdx.x;
    int c = g_assign[b * Tt + t];
    int lane = t & 31, w = t >> 5;
    int rank_in_warp = 0;
#pragma unroll
    for (int cc = 0; cc < 8; cc++) {
        unsigned m = __ballot_sync(0xffffffffu, c == cc);
        if (cc == c) rank_in_warp = __popc(m & ((1u << lane) - 1u));
        if (lane == 0) warp_hist[w][cc] = __popc(m);
    }
    __syncthreads();
    if (t < 8) {
        int s = 0;
        for (int ww = 0; ww < 32; ww++) s += warp_hist[ww][t];
        tot[t] = s;
        g_counts[b * Cc + t] = s;
    }
    __syncthreads();
    int before = 0;
    for (int ww = 0; ww < w; ww++) before += warp_hist[ww][c];
    int base = 0;
    for (int i = 0; i < c; i++) base += tot[i];
    g_list[b * Tt + base + before + rank_in_warp] = t;
}

// ---------------- 3/5) HMMA split GEMM, single-stage smem, 2 CTAs/SM -------
// MODE 0: A = X fp32 (cvt in-kernel), B = Win fp32 (cvt in-kernel).
// MODE 1: A = g_Chi/g_Clo bf16 planes (raw copy), B = Wout fp32 (cvt).
#define PLB   10240u
#define SBOF  20480u
#define GSM   40960u

template <int MODE>
__global__ void __launch_bounds__(256, 2) k_gemm_mma(
    const float* __restrict__ Asrc, const float* __restrict__ Bsrc,
    const float* __restrict__ bias, float* __restrict__ Co, int mbase) {
    extern __shared__ __align__(16) char dsm[];

    const int tid = threadIdx.x;
    const int lane = tid & 31, wid = tid >> 5;
    const int bm = (blockIdx.y + mbase) << 7, bn = blockIdx.x << 7;
    const int wm = (wid >> 2) << 6;
    const int wn = (wid & 3) << 5;

    const uint32_t sb = s2u(dsm);
    const int mq = lane >> 3, ri = lane & 7;
    const uint32_t aB0 = sb + (uint32_t)((wm + ((mq & 1) << 3) + ri) * 80 + ((mq >> 1) << 4));
    const uint32_t bB0 = sb + SBOF + (uint32_t)((wn + ((mq >> 1) << 3) + ri) * 80 + ((mq & 1) << 4));

    float acc[4][4][4];
#pragma unroll
    for (int i = 0; i < 4; i++)
#pragma unroll
        for (int j = 0; j < 4; j++)
#pragma unroll
            for (int q = 0; q < 4; q++) acc[i][j][q] = 0.f;

    const int row_ = tid >> 3, seg_ = tid & 7;
    auto cvst = [&](char* base, uint32_t off, float4 v) {
        uint32_t h0 = packbf(v.x, v.y), h1 = packbf(v.z, v.w);
        __nv_bfloat162 a01 = *(__nv_bfloat162*)&h0;
        __nv_bfloat162 a23 = *(__nv_bfloat162*)&h1;
        uint32_t l0 = packbf(v.x - __bfloat162float(a01.x), v.y - __bfloat162float(a01.y));
        uint32_t l1 = packbf(v.z - __bfloat162float(a23.x), v.w - __bfloat162float(a23.y));
        *(uint32_t*)(base + off)           = h0;
        *(uint32_t*)(base + off + 4)       = h1;
        *(uint32_t*)(base + off + PLB)     = l0;
        *(uint32_t*)(base + off + PLB + 4) = l1;
    };

    for (int kc = 0; kc < 16; kc++) {
        // ---- load next chunk into registers (latency overlaps sync wait) ----
        uint4 pa[4], pb[4];
#pragma unroll
        for (int r = 0; r < 4; r++) {
            if (MODE == 0) {
                int row = row_ + (r << 5);
                pa[r] = *(const uint4*)(Asrc + (size_t)(bm + row) * 512 + kc * 32 + (seg_ << 2));
            } else {
                int f = tid + (r << 8);
                int pl = f >> 9, rem = f & 511, row = rem >> 2, q = rem & 3;
                const __nv_bfloat16* src = pl ? g_Clo : g_Chi;
                pa[r] = *(const uint4*)(src + (size_t)(bm + row) * 512 + kc * 32 + q * 8);
            }
        }
#pragma unroll
        for (int r = 0; r < 4; r++) {
            int row = row_ + (r << 5);
            pb[r] = *(const uint4*)(Bsrc + (size_t)(bn + row) * 512 + kc * 32 + (seg_ << 2));
        }
        __syncthreads();   // all warps finished reading smem of previous kc
        // ---- convert/store to smem ----
#pragma unroll
        for (int r = 0; r < 4; r++) {
            if (MODE == 0) {
                int row = row_ + (r << 5);
                cvst(dsm, (uint32_t)(row * 80 + (seg_ << 3)), *(float4*)&pa[r]);
            } else {
                int f = tid + (r << 8);
                int pl = f >> 9, rem = f & 511, row = rem >> 2, q = rem & 3;
                *(uint4*)(dsm + pl * PLB + row * 80 + q * 16) = pa[r];
            }
            int row = row_ + (r << 5);
            cvst(dsm + SBOF, (uint32_t)(row * 80 + (seg_ << 3)), *(float4*)&pb[r]);
        }
        __syncthreads();
        // ---- MMA block: B frags resident, A frags streamed per M-slice ----
#pragma unroll
        for (int k16 = 0; k16 < 2; k16++) {
            uint32_t bh[4][2], bl[4][2];
#pragma unroll
            for (int j2 = 0; j2 < 2; j2++) {
                uint32_t bd = bB0 + j2 * (16 * 80) + k16 * 32;
                LDSM4(bh[j2 * 2][0], bh[j2 * 2][1], bh[j2 * 2 + 1][0], bh[j2 * 2 + 1][1], bd);
                LDSM4(bl[j2 * 2][0], bl[j2 * 2][1], bl[j2 * 2 + 1][0], bl[j2 * 2 + 1][1], bd + PLB);
            }
#pragma unroll
            for (int i = 0; i < 4; i++) {
                uint32_t ah[4], al[4];
                uint32_t ad = aB0 + i * (16 * 80) + k16 * 32;
                LDSM4(ah[0], ah[1], ah[2], ah[3], ad);
                LDSM4(al[0], al[1], al[2], al[3], ad + PLB);
#pragma unroll
                for (int j = 0; j < 4; j++) {
                    MMA16816(acc[i][j], ah, bh[j][0], bh[j][1]);
                    MMA16816(acc[i][j], ah, bl[j][0], bl[j][1]);
                    MMA16816(acc[i][j], al, bh[j][0], bh[j][1]);
                }
            }
        }
    }

    const int g = lane >> 2, q4 = lane & 3;
#pragma unroll
    for (int i = 0; i < 4; i++)
#pragma unroll
        for (int j = 0; j < 4; j++)
#pragma unroll
            for (int p = 0; p < 2; p++) {
                int m = bm + wm + i * 16 + g + p * 8;
                int n = bn + wn + j * 8 + q4 * 2;
                float2 v;
                v.x = acc[i][j][p * 2 + 0] + bias[n + 0];
                v.y = acc[i][j][p * 2 + 1] + bias[n + 1];
                if (MODE == 0) {
                    int part = n >> 9, nn = n & 511, h = nn >> 6, d = nn & 63;
                    int b_ = m >> 10, t = m & 1023;
                    size_t idx = (((size_t)(b_ * Hh + h) * Tt + t) << 6) + d;
                    uint32_t hv = packbf(v.x, v.y);
                    __nv_bfloat162 h2 = *(__nv_bfloat162*)&hv;
                    uint32_t lv = packbf(v.x - __bfloat162float(h2.x),
                                         v.y - __bfloat162float(h2.y));
                    __nv_bfloat16 *ph, *pl;
                    if (part == 0)      { ph = g_Qhi; pl = g_Qlo; }
                    else if (part == 1) { ph = g_Khi; pl = g_Klo; }
                    else                { ph = g_Vhi; pl = g_Vlo; }
                    *(uint32_t*)(ph + idx) = hv;
                    *(uint32_t*)(pl + idx) = lv;
                } else {
                    *(float2*)(Co + (size_t)m * 512 + n) = v;
                }
            }
}

// ---------------- 4) HMMA flash attention (r14 body) -----------------------
#define QPAD 72
__global__ void __launch_bounds__(128) k_attn(int bbase) {
    __shared__ __nv_bfloat16 sQ[2][64][QPAD];
    __shared__ __nv_bfloat16 sK[2][32][QPAD];
    __shared__ __nv_bfloat16 sV[2][32][QPAD];
    __shared__ int qtk[64];
    __shared__ int slist[1024];

    int bid = blockIdx.x;
    int qt = bid & 15, h = (bid >> 4) & 7, c = (bid >> 7) & 7;
    int b = bbase + (bid >> 10);
    int n = g_counts[b * Cc + c];
    if (qt * 64 >= n) return;
    int base = 0;
#pragma unroll
    for (int i = 0; i < Cc; i++) base += (i < c) ? g_counts[b * Cc + i] : 0;

    int tid = threadIdx.x, lane = tid & 31, wid = tid >> 5;
    for (int i = tid; i < n; i += 128) slist[i] = g_list[b * Tt + base + i];
    if (tid < 64) {
        int qi = qt * 64 + tid;
        qtk[tid] = (qi < n) ? g_list[b * Tt + base + qi] : -1;
    }
    __syncthreads();

    const size_t hb = ((size_t)(b * Hh + h)) << 16;
    const uint4 z4 = make_uint4(0, 0, 0, 0);
#pragma unroll
    for (int r = 0; r < 8; r++) {
        int f = tid + (r << 7);
        int pl = f >> 9, rem = f & 511, row = rem >> 3, seg = rem & 7;
        int tok = qtk[row];
        const __nv_bfloat16* src = pl ? g_Qlo : g_Qhi;
        uint4 v = (tok >= 0) ? *(const uint4*)(src + hb + ((size_t)tok << 6) + (seg << 3)) : z4;
        *(uint4*)&sQ[pl][row][seg << 3] = v;
    }
    __syncthreads();

    const int mq = lane >> 3, ri = lane & 7;
    const uint32_t QPLANE = 64 * QPAD * 2;
    const uint32_t KPLANE = 32 * QPAD * 2;
    uint32_t qb = s2u(&sQ[0][0][0]) +
                  (uint32_t)((wid * 16 + ((mq & 1) << 3) + ri) * (QPAD * 2) + ((mq >> 1) << 4));
    uint32_t qh[4][4], ql[4][4];
#pragma unroll
    for (int s = 0; s < 4; s++) {
        LDSM4(qh[s][0], qh[s][1], qh[s][2], qh[s][3], qb + s * 32);
        LDSM4(ql[s][0], ql[s][1], ql[s][2], ql[s][3], qb + QPLANE + s * 32);
    }

    uint32_t kb = s2u(&sK[0][0][0]) +
                  (uint32_t)((((mq >> 1) << 3) + ri) * (QPAD * 2) + ((mq & 1) << 4));
    uint32_t vb = s2u(&sV[0][0][0]) +
                  (uint32_t)(((((lane >> 3) & 1) << 3) + ri) * (QPAD * 2) + ((lane >> 4) << 4));

    float accO[8][4];
#pragma unroll
    for (int jo = 0; jo < 8; jo++)
#pragma unroll
        for (int q = 0; q < 4; q++) accO[jo][q] = 0.f;
    float m2[2] = {-1e30f, -1e30f}, l2[2] = {0.f, 0.f};

    uint4 pf[8];
    auto ldkv = [&](int kt) {
#pragma unroll
        for (int r = 0; r < 8; r++) {
            int f = tid + (r << 7);
            int pl = f >> 8, rem = f & 255, row = rem >> 3, seg = rem & 7;
            int ki = (kt << 5) + row;
            int tok = (ki < n) ? slist[ki] : -1;
            const __nv_bfloat16* src = (pl == 0) ? g_Khi : (pl == 1) ? g_Klo
                                     : (pl == 2) ? g_Vhi : g_Vlo;
            pf[r] = (tok >= 0) ? *(const uint4*)(src + hb + ((size_t)tok << 6) + (seg << 3)) : z4;
        }
    };
    ldkv(0);

    int nkt = (n + 31) >> 5;
    for (int kt = 0; kt < nkt; kt++) {
#pragma unroll
        for (int r = 0; r < 8; r++) {
            int f = tid + (r << 7);
            int pl = f >> 8, rem = f & 255, row = rem >> 3, seg = rem & 7;
            void* dst = (pl < 2) ? (void*)&sK[pl][row][seg << 3]
                                 : (void*)&sV[pl - 2][row][seg << 3];
            *(uint4*)dst = pf[r];
        }
        __syncthreads();
        if (kt + 1 < nkt) ldkv(kt + 1);

        float sf[4][4];
#pragma unroll
        for (int j = 0; j < 4; j++)
#pragma unroll
            for (int q = 0; q < 4; q++) sf[j][q] = 0.f;
#pragma unroll
        for (int s = 0; s < 4; s++) {
            uint32_t bh[4][2], bl[4][2];
#pragma unroll
            for (int np = 0; np < 2; np++) {
                uint32_t ad = kb + np * (16 * QPAD * 2) + s * 32;
                LDSM4(bh[np * 2][0], bh[np * 2][1], bh[np * 2 + 1][0], bh[np * 2 + 1][1], ad);
                LDSM4(bl[np * 2][0], bl[np * 2][1], bl[np * 2 + 1][0], bl[np * 2 + 1][1], ad + KPLANE);
            }
#pragma unroll
            for (int j = 0; j < 4; j++) {
                MMA16816(sf[j], qh[s], bh[j][0], bh[j][1]);
                MMA16816(sf[j], qh[s], bl[j][0], bl[j][1]);
                MMA16816(sf[j], ql[s], bh[j][0], bh[j][1]);
            }
        }
        int krem = n - (kt << 5);
#pragma unroll
        for (int j = 0; j < 4; j++)
#pragma unroll
            for (int q = 0; q < 4; q++) {
                int col = (j << 3) + ((lane & 3) << 1) + (q & 1);
                sf[j][q] = (col < krem) ? sf[j][q] * 0.125f : -1e30f;
            }
        float mx0 = -1e30f, mx1 = -1e30f;
#pragma unroll
        for (int j = 0; j < 4; j++) {
            mx0 = fmaxf(mx0, fmaxf(sf[j][0], sf[j][1]));
            mx1 = fmaxf(mx1, fmaxf(sf[j][2], sf[j][3]));
        }
        mx0 = fmaxf(mx0, __shfl_xor_sync(0xffffffffu, mx0, 1));
        mx0 = fmaxf(mx0, __shfl_xor_sync(0xffffffffu, mx0, 2));
        mx1 = fmaxf(mx1, __shfl_xor_sync(0xffffffffu, mx1, 1));
        mx1 = fmaxf(mx1, __shfl_xor_sync(0xffffffffu, mx1, 2));
        float mn0 = fmaxf(m2[0], mx0), mn1 = fmaxf(m2[1], mx1);
        float r0 = __expf(m2[0] - mn0), r1 = __expf(m2[1] - mn1);
        float rs0 = 0.f, rs1 = 0.f;
#pragma unroll
        for (int j = 0; j < 4; j++) {
            sf[j][0] = __expf(sf[j][0] - mn0); rs0 += sf[j][0];
            sf[j][1] = __expf(sf[j][1] - mn0); rs0 += sf[j][1];
            sf[j][2] = __expf(sf[j][2] - mn1); rs1 += sf[j][2];
            sf[j][3] = __expf(sf[j][3] - mn1); rs1 += sf[j][3];
        }
        rs0 += __shfl_xor_sync(0xffffffffu, rs0, 1);
        rs0 += __shfl_xor_sync(0xffffffffu, rs0, 2);
        rs1 += __shfl_xor_sync(0xffffffffu, rs1, 1);
        rs1 += __shfl_xor_sync(0xffffffffu, rs1, 2);
        l2[0] = l2[0] * r0 + rs0;
        l2[1] = l2[1] * r1 + rs1;
        m2[0] = mn0; m2[1] = mn1;
#pragma unroll
        for (int jo = 0; jo < 8; jo++) {
            accO[jo][0] *= r0; accO[jo][1] *= r0;
            accO[jo][2] *= r1; accO[jo][3] *= r1;
        }
        uint32_t ph[2][4], plo[2][4];
#pragma unroll
        for (int s2 = 0; s2 < 2; s2++) {
            float c0a = sf[2 * s2][0],     c1a = sf[2 * s2][1];
            float c2a = sf[2 * s2][2],     c3a = sf[2 * s2][3];
            float c0b = sf[2 * s2 + 1][0], c1b = sf[2 * s2 + 1][1];
            float c2b = sf[2 * s2 + 1][2], c3b = sf[2 * s2 + 1][3];
            ph[s2][0] = packbf(c0a, c1a); ph[s2][1] = packbf(c2a, c3a);
            ph[s2][2] = packbf(c0b, c1b); ph[s2][3] = packbf(c2b, c3b);
            __nv_bfloat162 t0 = *(__nv_bfloat162*)&ph[s2][0];
            __nv_bfloat162 t1 = *(__nv_bfloat162*)&ph[s2][1];
            __nv_bfloat162 t2 = *(__nv_bfloat162*)&ph[s2][2];
            __nv_bfloat162 t3 = *(__nv_bfloat162*)&ph[s2][3];
            plo[s2][0] = packbf(c0a - __bfloat162float(t0.x), c1a - __bfloat162float(t0.y));
            plo[s2][1] = packbf(c2a - __bfloat162float(t1.x), c3a - __bfloat162float(t1.y));
            plo[s2][2] = packbf(c0b - __bfloat162float(t2.x), c1b - __bfloat162float(t2.y));
            plo[s2][3] = packbf(c2b - __bfloat162float(t3.x), c3b - __bfloat162float(t3.y));
        }
#pragma unroll
        for (int s2 = 0; s2 < 2; s2++) {
#pragma unroll
            for (int jp = 0; jp < 4; jp++) {
                uint32_t vh0, vh1, vh2, vh3, vl0, vl1, vl2, vl3;
                uint32_t ad = vb + s2 * (16 * QPAD * 2) + jp * 32;
                LDSM4T(vh0, vh1, vh2, vh3, ad);
                LDSM4T(vl0, vl1, vl2, vl3, ad + KPLANE);
                MMA16816(accO[2 * jp],     ph[s2],  vh0, vh1);
                MMA16816(accO[2 * jp],     ph[s2],  vl0, vl1);
                MMA16816(accO[2 * jp],     plo[s2], vh0, vh1);
                MMA16816(accO[2 * jp + 1], ph[s2],  vh2, vh3);
                MMA16816(accO[2 * jp + 1], ph[s2],  vl2, vl3);
                MMA16816(accO[2 * jp + 1], plo[s2], vh2, vh3);
            }
        }
        __syncthreads();
    }
    float M0 = fmaxf(m2[0], 0.f), M1 = fmaxf(m2[1], 0.f);
    float e0 = __expf(m2[0] - M0), e1 = __expf(m2[1] - M1);
    float f0 = e0 / (l2[0] * e0 + (float)(Tt - n) * __expf(-M0));
    float f1 = e1 / (l2[1] * e1 + (float)(Tt - n) * __expf(-M1));
    int g = lane >> 2;
    int row0 = wid * 16 + g, row1 = row0 + 8;
    int t0 = qtk[row0], t1 = qtk[row1];
#pragma unroll
    for (int jo = 0; jo < 8; jo++) {
        int col = (jo << 3) + ((lane & 3) << 1);
        if (t0 >= 0) {
            float vx = accO[jo][0] * f0, vy = accO[jo][1] * f0;
            size_t idx = ((size_t)(b * Tt + t0)) * Dd + (h << 6) + col;
            uint32_t hv = packbf(vx, vy);
            __nv_bfloat162 h2 = *(__nv_bfloat162*)&hv;
            uint32_t lv = packbf(vx - __bfloat162float(h2.x), vy - __bfloat162float(h2.y));
            *(uint32_t*)(g_Chi + idx) = hv;
            *(uint32_t*)(g_Clo + idx) = lv;
        }
        if (t1 >= 0) {
            float vx = accO[jo][2] * f1, vy = accO[jo][3] * f1;
            size_t idx = ((size_t)(b * Tt + t1)) * Dd + (h << 6) + col;
            uint32_t hv = packbf(vx, vy);
            __nv_bfloat162 h2 = *(__nv_bfloat162*)&hv;
            uint32_t lv = packbf(vx - __bfloat162float(h2.x), vy - __bfloat162float(h2.y));
            *(uint32_t*)(g_Chi + idx) = hv;
            *(uint32_t*)(g_Clo + idx) = lv;
        }
    }
}

// ---------------- launch: 2-group pipelined (9 nodes, 3 streams) -----------
extern "C" void kernel_launch(void* const* d_in, const int* in_sizes, int n_in,
                              void* d_out, int out_size) {
    const float* X    = (const float*)d_in[0];
    const float* Wc   = (const float*)d_in[1];
    const float* bc   = (const float*)d_in[2];
    const float* Win  = (const float*)d_in[3];
    const float* bin  = (const float*)d_in[4];
    const float* Wout = (const float*)d_in[5];
    const float* bout = (const float*)d_in[6];
    float* out = (float*)d_out;

    static cudaStream_t s2 = nullptr, st1 = nullptr;
    static cudaEvent_t eFork = nullptr, eRank = nullptr, eD1 = nullptr;
    if (s2 == nullptr) {
        cudaStreamCreateWithFlags(&s2,  cudaStreamNonBlocking);
        cudaStreamCreateWithFlags(&st1, cudaStreamNonBlocking);
        cudaEventCreateWithFlags(&eFork, cudaEventDisableTiming);
        cudaEventCreateWithFlags(&eRank, cudaEventDisableTiming);
        cudaEventCreateWithFlags(&eD1, cudaEventDisableTiming);
    }

    cudaEventRecord(eFork, 0);
    cudaStreamWaitEvent(s2, eFork, 0);
    cudaStreamWaitEvent(st1, eFork, 0);

    // cluster assignment branch
    k_assign<<<(Bc * Tt) / 8, 256, 0, s2>>>(X, Wc, bc);
    k_rank<<<Bc, 1024, 0, s2>>>();
    cudaEventRecord(eRank, s2);

    // group 0 = batches {0,1} on main, group 1 = batches {2,3} on st1
    k_gemm_mma<0><<<dim3(12, 16), 256, GSM, 0>>>(X, Win, bin, nullptr, 0);
    k_gemm_mma<0><<<dim3(12, 16), 256, GSM, st1>>>(X, Win, bin, nullptr, 16);

    cudaStreamWaitEvent(0, eRank, 0);
    k_attn<<<2048, 128, 0, 0>>>(0);
    k_gemm_mma<1><<<dim3(4, 16), 256, GSM, 0>>>(nullptr, Wout, bout, out, 0);

    cudaStreamWaitEvent(st1, eRank, 0);
    k_attn<<<2048, 128, 0, st1>>>(2);
    k_gemm_mma<1><<<dim3(4, 16), 256, GSM, st1>>>(nullptr, Wout, bout, out, 16);
    cudaEventRecord(eD1, st1);

    cudaStreamWaitEvent(0, eD1, 0);
}

// round 16
// speedup vs baseline: 1.0478x; 1.0478x over previous
#include <cuda_runtime.h>
#include <cuda_bf16.h>
#include <cstdint>

#define Bc 4
#define Tt 1024
#define Dd 512
#define Cc 8
#define Hh 8

// ---------------- scratch (device globals) ---------------------------------
__device__ int   g_assign[Bc * Tt];
__device__ int   g_counts[Bc * Cc];
__device__ int   g_list[Bc * Tt];
#define PLN (Bc * Hh * Tt * 64)
__device__ __nv_bfloat16 g_Qhi[PLN], g_Qlo[PLN];
__device__ __nv_bfloat16 g_Khi[PLN], g_Klo[PLN];
__device__ __nv_bfloat16 g_Vhi[PLN], g_Vlo[PLN];
__device__ __nv_bfloat16 g_Chi[Bc * Tt * Dd], g_Clo[Bc * Tt * Dd];

static __device__ __forceinline__ uint32_t s2u(const void* p) {
    uint32_t a;
    asm("{ .reg .u64 t; cvta.to.shared.u64 t, %1; cvt.u32.u64 %0, t; }" : "=r"(a) : "l"(p));
    return a;
}
#define LDSM4(r0, r1, r2, r3, addr) \
    asm volatile("ldmatrix.sync.aligned.m8n8.x4.shared.b16 {%0,%1,%2,%3}, [%4];" \
                 : "=r"(r0), "=r"(r1), "=r"(r2), "=r"(r3) : "r"(addr))
#define LDSM4T(r0, r1, r2, r3, addr) \
    asm volatile("ldmatrix.sync.aligned.m8n8.x4.trans.shared.b16 {%0,%1,%2,%3}, [%4];" \
                 : "=r"(r0), "=r"(r1), "=r"(r2), "=r"(r3) : "r"(addr))
#define MMA16816(d, a, b0, b1) \
    asm volatile("mma.sync.aligned.m16n8k16.row.col.f32.bf16.bf16.f32 " \
                 "{%0,%1,%2,%3}, {%4,%5,%6,%7}, {%8,%9}, {%0,%1,%2,%3};" \
                 : "+f"((d)[0]), "+f"((d)[1]), "+f"((d)[2]), "+f"((d)[3]) \
                 : "r"((a)[0]), "r"((a)[1]), "r"((a)[2]), "r"((a)[3]), \
                   "r"((b0)), "r"((b1)))

static __device__ __forceinline__ uint32_t packbf(float x, float y) {
    __nv_bfloat162 t = __halves2bfloat162(__float2bfloat16(x), __float2bfloat16(y));
    return *(uint32_t*)&t;
}

// ---------------- 1) cluster argmax (fp32 Kahan) ---------------------------
__global__ void k_assign(const float* __restrict__ X,
                         const float* __restrict__ Wc,
                         const float* __restrict__ bc) {
    int gw   = (blockIdx.x * blockDim.x + threadIdx.x) >> 5;
    int lane = threadIdx.x & 31;
    if (gw >= Bc * Tt) return;
    const float4* x4 = (const float4*)(X + (size_t)gw * Dd);
    float4 xr[4];
#pragma unroll
    for (int r = 0; r < 4; r++) xr[r] = x4[lane + (r << 5)];
    float best = -1e30f; int bi = 0;
#pragma unroll
    for (int c = 0; c < Cc; c++) {
        const float4* w4 = (const float4*)(Wc + c * Dd);
        float sum = 0.f, comp = 0.f;
#pragma unroll
        for (int r = 0; r < 4; r++) {
            float4 w = w4[lane + (r << 5)];
            float pr[4] = {xr[r].x * w.x, xr[r].y * w.y, xr[r].z * w.z, xr[r].w * w.w};
#pragma unroll
            for (int q = 0; q < 4; q++) {
                float y = pr[q] - comp;
                float t = sum + y;
                comp = (t - sum) - y;
                sum = t;
            }
        }
#pragma unroll
        for (int o = 16; o; o >>= 1) sum += __shfl_xor_sync(0xffffffffu, sum, o);
        float s = sum + bc[c];
        if (s > best) { best = s; bi = c; }
    }
    if (lane == 0) g_assign[gw] = bi;
}

// ---------------- 2) stable per-cluster rank via ballots -------------------
__global__ void __launch_bounds__(1024) k_rank() {
    __shared__ int warp_hist[32][8];
    __shared__ int tot[8];
    int b = blockIdx.x, t = threadIdx.x;
    int c = g_assign[b * Tt + t];
    int lane = t & 31, w = t >> 5;
    int rank_in_warp = 0;
#pragma unroll
    for (int cc = 0; cc < 8; cc++) {
        unsigned m = __ballot_sync(0xffffffffu, c == cc);
        if (cc == c) rank_in_warp = __popc(m & ((1u << lane) - 1u));
        if (lane == 0) warp_hist[w][cc] = __popc(m);
    }
    __syncthreads();
    if (t < 8) {
        int s = 0;
        for (int ww = 0; ww < 32; ww++) s += warp_hist[ww][t];
        tot[t] = s;
        g_counts[b * Cc + t] = s;
    }
    __syncthreads();
    int before = 0;
    for (int ww = 0; ww < w; ww++) before += warp_hist[ww][c];
    int base = 0;
    for (int i = 0; i < c; i++) base += tot[i];
    g_list[b * Tt + base + before + rank_in_warp] = t;
}

#define PLB   10240u
#define SBOF  20480u
#define STG   40960u
#define GSM0  40960u          // gemm0: single stage
#define GSM1  (2 * STG)       // gemm1: double buffered

// ---------------- 3) gemm0: single-stage smem, 2 CTAs/SM (r15 winner) ------
// A = X fp32 (cvt in-kernel), B = Win fp32 (cvt in-kernel) -> QKV planes.
__global__ void __launch_bounds__(256, 2) k_gemm0(
    const float* __restrict__ Asrc, const float* __restrict__ Bsrc,
    const float* __restrict__ bias, int mbase) {
    extern __shared__ __align__(16) char dsm[];

    const int tid = threadIdx.x;
    const int lane = tid & 31, wid = tid >> 5;
    const int bm = (blockIdx.y + mbase) << 7, bn = blockIdx.x << 7;
    const int wm = (wid >> 2) << 6;
    const int wn = (wid & 3) << 5;

    const uint32_t sb = s2u(dsm);
    const int mq = lane >> 3, ri = lane & 7;
    const uint32_t aB0 = sb + (uint32_t)((wm + ((mq & 1) << 3) + ri) * 80 + ((mq >> 1) << 4));
    const uint32_t bB0 = sb + SBOF + (uint32_t)((wn + ((mq >> 1) << 3) + ri) * 80 + ((mq & 1) << 4));

    float acc[4][4][4];
#pragma unroll
    for (int i = 0; i < 4; i++)
#pragma unroll
        for (int j = 0; j < 4; j++)
#pragma unroll
            for (int q = 0; q < 4; q++) acc[i][j][q] = 0.f;

    const int row_ = tid >> 3, seg_ = tid & 7;
    auto cvst = [&](char* base, uint32_t off, float4 v) {
        uint32_t h0 = packbf(v.x, v.y), h1 = packbf(v.z, v.w);
        __nv_bfloat162 a01 = *(__nv_bfloat162*)&h0;
        __nv_bfloat162 a23 = *(__nv_bfloat162*)&h1;
        uint32_t l0 = packbf(v.x - __bfloat162float(a01.x), v.y - __bfloat162float(a01.y));
        uint32_t l1 = packbf(v.z - __bfloat162float(a23.x), v.w - __bfloat162float(a23.y));
        *(uint32_t*)(base + off)           = h0;
        *(uint32_t*)(base + off + 4)       = h1;
        *(uint32_t*)(base + off + PLB)     = l0;
        *(uint32_t*)(base + off + PLB + 4) = l1;
    };

    for (int kc = 0; kc < 16; kc++) {
        uint4 pa[4], pb[4];
#pragma unroll
        for (int r = 0; r < 4; r++) {
            int row = row_ + (r << 5);
            pa[r] = *(const uint4*)(Asrc + (size_t)(bm + row) * 512 + kc * 32 + (seg_ << 2));
            pb[r] = *(const uint4*)(Bsrc + (size_t)(bn + row) * 512 + kc * 32 + (seg_ << 2));
        }
        __syncthreads();
#pragma unroll
        for (int r = 0; r < 4; r++) {
            int row = row_ + (r << 5);
            cvst(dsm, (uint32_t)(row * 80 + (seg_ << 3)), *(float4*)&pa[r]);
            cvst(dsm + SBOF, (uint32_t)(row * 80 + (seg_ << 3)), *(float4*)&pb[r]);
        }
        __syncthreads();
#pragma unroll
        for (int k16 = 0; k16 < 2; k16++) {
            uint32_t bh[4][2], bl[4][2];
#pragma unroll
            for (int j2 = 0; j2 < 2; j2++) {
                uint32_t bd = bB0 + j2 * (16 * 80) + k16 * 32;
                LDSM4(bh[j2 * 2][0], bh[j2 * 2][1], bh[j2 * 2 + 1][0], bh[j2 * 2 + 1][1], bd);
                LDSM4(bl[j2 * 2][0], bl[j2 * 2][1], bl[j2 * 2 + 1][0], bl[j2 * 2 + 1][1], bd + PLB);
            }
#pragma unroll
            for (int i = 0; i < 4; i++) {
                uint32_t ah[4], al[4];
                uint32_t ad = aB0 + i * (16 * 80) + k16 * 32;
                LDSM4(ah[0], ah[1], ah[2], ah[3], ad);
                LDSM4(al[0], al[1], al[2], al[3], ad + PLB);
#pragma unroll
                for (int j = 0; j < 4; j++) {
                    MMA16816(acc[i][j], ah, bh[j][0], bh[j][1]);
                    MMA16816(acc[i][j], ah, bl[j][0], bl[j][1]);
                    MMA16816(acc[i][j], al, bh[j][0], bh[j][1]);
                }
            }
        }
    }

    const int g = lane >> 2, q4 = lane & 3;
#pragma unroll
    for (int i = 0; i < 4; i++)
#pragma unroll
        for (int j = 0; j < 4; j++)
#pragma unroll
            for (int p = 0; p < 2; p++) {
                int m = bm + wm + i * 16 + g + p * 8;
                int n = bn + wn + j * 8 + q4 * 2;
                float2 v;
                v.x = acc[i][j][p * 2 + 0] + bias[n + 0];
                v.y = acc[i][j][p * 2 + 1] + bias[n + 1];
                int part = n >> 9, nn = n & 511, h = nn >> 6, d = nn & 63;
                int b_ = m >> 10, t = m & 1023;
                size_t idx = (((size_t)(b_ * Hh + h) * Tt + t) << 6) + d;
                uint32_t hv = packbf(v.x, v.y);
                __nv_bfloat162 h2 = *(__nv_bfloat162*)&hv;
                uint32_t lv = packbf(v.x - __bfloat162float(h2.x),
                                     v.y - __bfloat162float(h2.y));
                __nv_bfloat16 *ph, *pl;
                if (part == 0)      { ph = g_Qhi; pl = g_Qlo; }
                else if (part == 1) { ph = g_Khi; pl = g_Klo; }
                else                { ph = g_Vhi; pl = g_Vlo; }
                *(uint32_t*)(ph + idx) = hv;
                *(uint32_t*)(pl + idx) = lv;
            }
}

// ---------------- 5) gemm1: double-buffered (r14 MODE-1 body) --------------
// A = g_Chi/g_Clo bf16 planes (raw copy), B = Wout fp32 (cvt).
__global__ void __launch_bounds__(256) k_gemm1(
    const float* __restrict__ Bsrc, const float* __restrict__ bias,
    float* __restrict__ Co, int mbase) {
    extern __shared__ __align__(16) char dsm[];

    const int tid = threadIdx.x;
    const int lane = tid & 31, wid = tid >> 5;
    const int bm = (blockIdx.y + mbase) << 7, bn = blockIdx.x << 7;
    const int wm = (wid >> 2) << 6;
    const int wn = (wid & 3) << 5;

    const uint32_t sb = s2u(dsm);
    const int mq = lane >> 3, ri = lane & 7;
    const uint32_t aB0 = (uint32_t)((wm + ((mq & 1) << 3) + ri) * 80 + ((mq >> 1) << 4));
    const uint32_t bB0 = SBOF + (uint32_t)((wn + ((mq >> 1) << 3) + ri) * 80 + ((mq & 1) << 4));

    float acc[4][4][4];
#pragma unroll
    for (int i = 0; i < 4; i++)
#pragma unroll
        for (int j = 0; j < 4; j++)
#pragma unroll
            for (int q = 0; q < 4; q++) acc[i][j][q] = 0.f;

    const int row_ = tid >> 3, seg_ = tid & 7;
    auto cvst = [&](char* base, uint32_t off, float4 v) {
        uint32_t h0 = packbf(v.x, v.y), h1 = packbf(v.z, v.w);
        __nv_bfloat162 a01 = *(__nv_bfloat162*)&h0;
        __nv_bfloat162 a23 = *(__nv_bfloat162*)&h1;
        uint32_t l0 = packbf(v.x - __bfloat162float(a01.x), v.y - __bfloat162float(a01.y));
        uint32_t l1 = packbf(v.z - __bfloat162float(a23.x), v.w - __bfloat162float(a23.y));
        *(uint32_t*)(base + off)           = h0;
        *(uint32_t*)(base + off + 4)       = h1;
        *(uint32_t*)(base + off + PLB)     = l0;
        *(uint32_t*)(base + off + PLB + 4) = l1;
    };

    uint4 pa[4], pb[4];
    auto ldA = [&](int kc) {
#pragma unroll
        for (int r = 0; r < 4; r++) {
            int f = tid + (r << 8);
            int pl = f >> 9, rem = f & 511, row = rem >> 2, q = rem & 3;
            const __nv_bfloat16* src = pl ? g_Clo : g_Chi;
            pa[r] = *(const uint4*)(src + (size_t)(bm + row) * 512 + kc * 32 + q * 8);
        }
    };
    auto ldB = [&](int kc) {
#pragma unroll
        for (int r = 0; r < 4; r++) {
            int row = row_ + (r << 5);
            pb[r] = *(const uint4*)(Bsrc + (size_t)(bn + row) * 512 + kc * 32 + (seg_ << 2));
        }
    };
    auto stAB = [&](char* base) {
#pragma unroll
        for (int r = 0; r < 4; r++) {
            int f = tid + (r << 8);
            int pl = f >> 9, rem = f & 511, row = rem >> 2, q = rem & 3;
            *(uint4*)(base + pl * PLB + row * 80 + q * 16) = pa[r];
            int row2 = row_ + (r << 5);
            cvst(base + SBOF, (uint32_t)(row2 * 80 + (seg_ << 3)), *(float4*)&pb[r]);
        }
    };

    ldA(0); ldB(0);
    stAB(dsm);
    __syncthreads();

    for (int kc = 0; kc < 16; kc++) {
        if (kc < 15) { ldA(kc + 1); ldB(kc + 1); }
        const uint32_t stg = sb + (kc & 1) * STG;
#pragma unroll
        for (int k16 = 0; k16 < 2; k16++) {
            uint32_t ah[4][4], al[4][4], bh[4][2], bl[4][2];
#pragma unroll
            for (int i = 0; i < 4; i++) {
                uint32_t ad = stg + aB0 + i * (16 * 80) + k16 * 32;
                LDSM4(ah[i][0], ah[i][1], ah[i][2], ah[i][3], ad);
                LDSM4(al[i][0], al[i][1], al[i][2], al[i][3], ad + PLB);
            }
#pragma unroll
            for (int j2 = 0; j2 < 2; j2++) {
                uint32_t bd = stg + bB0 + j2 * (16 * 80) + k16 * 32;
                LDSM4(bh[j2 * 2][0], bh[j2 * 2][1], bh[j2 * 2 + 1][0], bh[j2 * 2 + 1][1], bd);
                LDSM4(bl[j2 * 2][0], bl[j2 * 2][1], bl[j2 * 2 + 1][0], bl[j2 * 2 + 1][1], bd + PLB);
            }
#pragma unroll
            for (int i = 0; i < 4; i++)
#pragma unroll
                for (int j = 0; j < 4; j++) {
                    MMA16816(acc[i][j], ah[i], bh[j][0], bh[j][1]);
                    MMA16816(acc[i][j], ah[i], bl[j][0], bl[j][1]);
                    MMA16816(acc[i][j], al[i], bh[j][0], bh[j][1]);
                }
        }
        if (kc < 15) stAB(dsm + ((kc + 1) & 1) * STG);
        __syncthreads();
    }

    const int g = lane >> 2, q4 = lane & 3;
#pragma unroll
    for (int i = 0; i < 4; i++)
#pragma unroll
        for (int j = 0; j < 4; j++)
#pragma unroll
            for (int p = 0; p < 2; p++) {
                int m = bm + wm + i * 16 + g + p * 8;
                int n = bn + wn + j * 8 + q4 * 2;
                float2 v;
                v.x = acc[i][j][p * 2 + 0] + bias[n + 0];
                v.y = acc[i][j][p * 2 + 1] + bias[n + 1];
                *(float2*)(Co + (size_t)m * 512 + n) = v;
            }
}

// ---------------- 4) HMMA flash attention (r14 body) -----------------------
#define QPAD 72
__global__ void __launch_bounds__(128) k_attn(int bbase) {
    __shared__ __nv_bfloat16 sQ[2][64][QPAD];
    __shared__ __nv_bfloat16 sK[2][32][QPAD];
    __shared__ __nv_bfloat16 sV[2][32][QPAD];
    __shared__ int qtk[64];
    __shared__ int slist[1024];

    int bid = blockIdx.x;
    int qt = bid & 15, h = (bid >> 4) & 7, c = (bid >> 7) & 7;
    int b = bbase + (bid >> 10);
    int n = g_counts[b * Cc + c];
    if (qt * 64 >= n) return;
    int base = 0;
#pragma unroll
    for (int i = 0; i < Cc; i++) base += (i < c) ? g_counts[b * Cc + i] : 0;

    int tid = threadIdx.x, lane = tid & 31, wid = tid >> 5;
    for (int i = tid; i < n; i += 128) slist[i] = g_list[b * Tt + base + i];
    if (tid < 64) {
        int qi = qt * 64 + tid;
        qtk[tid] = (qi < n) ? g_list[b * Tt + base + qi] : -1;
    }
    __syncthreads();

    const size_t hb = ((size_t)(b * Hh + h)) << 16;
    const uint4 z4 = make_uint4(0, 0, 0, 0);
#pragma unroll
    for (int r = 0; r < 8; r++) {
        int f = tid + (r << 7);
        int pl = f >> 9, rem = f & 511, row = rem >> 3, seg = rem & 7;
        int tok = qtk[row];
        const __nv_bfloat16* src = pl ? g_Qlo : g_Qhi;
        uint4 v = (tok >= 0) ? *(const uint4*)(src + hb + ((size_t)tok << 6) + (seg << 3)) : z4;
        *(uint4*)&sQ[pl][row][seg << 3] = v;
    }
    __syncthreads();

    const int mq = lane >> 3, ri = lane & 7;
    const uint32_t QPLANE = 64 * QPAD * 2;
    const uint32_t KPLANE = 32 * QPAD * 2;
    uint32_t qb = s2u(&sQ[0][0][0]) +
                  (uint32_t)((wid * 16 + ((mq & 1) << 3) + ri) * (QPAD * 2) + ((mq >> 1) << 4));
    uint32_t qh[4][4], ql[4][4];
#pragma unroll
    for (int s = 0; s < 4; s++) {
        LDSM4(qh[s][0], qh[s][1], qh[s][2], qh[s][3], qb + s * 32);
        LDSM4(ql[s][0], ql[s][1], ql[s][2], ql[s][3], qb + QPLANE + s * 32);
    }

    uint32_t kb = s2u(&sK[0][0][0]) +
                  (uint32_t)((((mq >> 1) << 3) + ri) * (QPAD * 2) + ((mq & 1) << 4));
    uint32_t vb = s2u(&sV[0][0][0]) +
                  (uint32_t)(((((lane >> 3) & 1) << 3) + ri) * (QPAD * 2) + ((lane >> 4) << 4));

    float accO[8][4];
#pragma unroll
    for (int jo = 0; jo < 8; jo++)
#pragma unroll
        for (int q = 0; q < 4; q++) accO[jo][q] = 0.f;
    float m2[2] = {-1e30f, -1e30f}, l2[2] = {0.f, 0.f};

    uint4 pf[8];
    auto ldkv = [&](int kt) {
#pragma unroll
        for (int r = 0; r < 8; r++) {
            int f = tid + (r << 7);
            int pl = f >> 8, rem = f & 255, row = rem >> 3, seg = rem & 7;
            int ki = (kt << 5) + row;
            int tok = (ki < n) ? slist[ki] : -1;
            const __nv_bfloat16* src = (pl == 0) ? g_Khi : (pl == 1) ? g_Klo
                                     : (pl == 2) ? g_Vhi : g_Vlo;
            pf[r] = (tok >= 0) ? *(const uint4*)(src + hb + ((size_t)tok << 6) + (seg << 3)) : z4;
        }
    };
    ldkv(0);

    int nkt = (n + 31) >> 5;
    for (int kt = 0; kt < nkt; kt++) {
#pragma unroll
        for (int r = 0; r < 8; r++) {
            int f = tid + (r << 7);
            int pl = f >> 8, rem = f & 255, row = rem >> 3, seg = rem & 7;
            void* dst = (pl < 2) ? (void*)&sK[pl][row][seg << 3]
                                 : (void*)&sV[pl - 2][row][seg << 3];
            *(uint4*)dst = pf[r];
        }
        __syncthreads();
        if (kt + 1 < nkt) ldkv(kt + 1);

        float sf[4][4];
#pragma unroll
        for (int j = 0; j < 4; j++)
#pragma unroll
            for (int q = 0; q < 4; q++) sf[j][q] = 0.f;
#pragma unroll
        for (int s = 0; s < 4; s++) {
            uint32_t bh[4][2], bl[4][2];
#pragma unroll
            for (int np = 0; np < 2; np++) {
                uint32_t ad = kb + np * (16 * QPAD * 2) + s * 32;
                LDSM4(bh[np * 2][0], bh[np * 2][1], bh[np * 2 + 1][0], bh[np * 2 + 1][1], ad);
                LDSM4(bl[np * 2][0], bl[np * 2][1], bl[np * 2 + 1][0], bl[np * 2 + 1][1], ad + KPLANE);
            }
#pragma unroll
            for (int j = 0; j < 4; j++) {
                MMA16816(sf[j], qh[s], bh[j][0], bh[j][1]);
                MMA16816(sf[j], qh[s], bl[j][0], bl[j][1]);
                MMA16816(sf[j], ql[s], bh[j][0], bh[j][1]);
            }
        }
        int krem = n - (kt << 5);
#pragma unroll
        for (int j = 0; j < 4; j++)
#pragma unroll
            for (int q = 0; q < 4; q++) {
                int col = (j << 3) + ((lane & 3) << 1) + (q & 1);
                sf[j][q] = (col < krem) ? sf[j][q] * 0.125f : -1e30f;
            }
        float mx0 = -1e30f, mx1 = -1e30f;
#pragma unroll
        for (int j = 0; j < 4; j++) {
            mx0 = fmaxf(mx0, fmaxf(sf[j][0], sf[j][1]));
            mx1 = fmaxf(mx1, fmaxf(sf[j][2], sf[j][3]));
        }
        mx0 = fmaxf(mx0, __shfl_xor_sync(0xffffffffu, mx0, 1));
        mx0 = fmaxf(mx0, __shfl_xor_sync(0xffffffffu, mx0, 2));
        mx1 = fmaxf(mx1, __shfl_xor_sync(0xffffffffu, mx1, 1));
        mx1 = fmaxf(mx1, __shfl_xor_sync(0xffffffffu, mx1, 2));
        float mn0 = fmaxf(m2[0], mx0), mn1 = fmaxf(m2[1], mx1);
        float r0 = __expf(m2[0] - mn0), r1 = __expf(m2[1] - mn1);
        float rs0 = 0.f, rs1 = 0.f;
#pragma unroll
        for (int j = 0; j < 4; j++) {
            sf[j][0] = __expf(sf[j][0] - mn0); rs0 += sf[j][0];
            sf[j][1] = __expf(sf[j][1] - mn0); rs0 += sf[j][1];
            sf[j][2] = __expf(sf[j][2] - mn1); rs1 += sf[j][2];
            sf[j][3] = __expf(sf[j][3] - mn1); rs1 += sf[j][3];
        }
        rs0 += __shfl_xor_sync(0xffffffffu, rs0, 1);
        rs0 += __shfl_xor_sync(0xffffffffu, rs0, 2);
        rs1 += __shfl_xor_sync(0xffffffffu, rs1, 1);
        rs1 += __shfl_xor_sync(0xffffffffu, rs1, 2);
        l2[0] = l2[0] * r0 + rs0;
        l2[1] = l2[1] * r1 + rs1;
        m2[0] = mn0; m2[1] = mn1;
#pragma unroll
        for (int jo = 0; jo < 8; jo++) {
            accO[jo][0] *= r0; accO[jo][1] *= r0;
            accO[jo][2] *= r1; accO[jo][3] *= r1;
        }
        uint32_t ph[2][4], plo[2][4];
#pragma unroll
        for (int s2 = 0; s2 < 2; s2++) {
            float c0a = sf[2 * s2][0],     c1a = sf[2 * s2][1];
            float c2a = sf[2 * s2][2],     c3a = sf[2 * s2][3];
            float c0b = sf[2 * s2 + 1][0], c1b = sf[2 * s2 + 1][1];
            float c2b = sf[2 * s2 + 1][2], c3b = sf[2 * s2 + 1][3];
            ph[s2][0] = packbf(c0a, c1a); ph[s2][1] = packbf(c2a, c3a);
            ph[s2][2] = packbf(c0b, c1b); ph[s2][3] = packbf(c2b, c3b);
            __nv_bfloat162 t0 = *(__nv_bfloat162*)&ph[s2][0];
            __nv_bfloat162 t1 = *(__nv_bfloat162*)&ph[s2][1];
            __nv_bfloat162 t2 = *(__nv_bfloat162*)&ph[s2][2];
            __nv_bfloat162 t3 = *(__nv_bfloat162*)&ph[s2][3];
            plo[s2][0] = packbf(c0a - __bfloat162float(t0.x), c1a - __bfloat162float(t0.y));
            plo[s2][1] = packbf(c2a - __bfloat162float(t1.x), c3a - __bfloat162float(t1.y));
            plo[s2][2] = packbf(c0b - __bfloat162float(t2.x), c1b - __bfloat162float(t2.y));
            plo[s2][3] = packbf(c2b - __bfloat162float(t3.x), c3b - __bfloat162float(t3.y));
        }
#pragma unroll
        for (int s2 = 0; s2 < 2; s2++) {
#pragma unroll
            for (int jp = 0; jp < 4; jp++) {
                uint32_t vh0, vh1, vh2, vh3, vl0, vl1, vl2, vl3;
                uint32_t ad = vb + s2 * (16 * QPAD * 2) + jp * 32;
                LDSM4T(vh0, vh1, vh2, vh3, ad);
                LDSM4T(vl0, vl1, vl2, vl3, ad + KPLANE);
                MMA16816(accO[2 * jp],     ph[s2],  vh0, vh1);
                MMA16816(accO[2 * jp],     ph[s2],  vl0, vl1);
                MMA16816(accO[2 * jp],     plo[s2], vh0, vh1);
                MMA16816(accO[2 * jp + 1], ph[s2],  vh2, vh3);
                MMA16816(accO[2 * jp + 1], ph[s2],  vl2, vl3);
                MMA16816(accO[2 * jp + 1], plo[s2], vh2, vh3);
            }
        }
        __syncthreads();
    }
    float M0 = fmaxf(m2[0], 0.f), M1 = fmaxf(m2[1], 0.f);
    float e0 = __expf(m2[0] - M0), e1 = __expf(m2[1] - M1);
    float f0 = e0 / (l2[0] * e0 + (float)(Tt - n) * __expf(-M0));
    float f1 = e1 / (l2[1] * e1 + (float)(Tt - n) * __expf(-M1));
    int g = lane >> 2;
    int row0 = wid * 16 + g, row1 = row0 + 8;
    int t0 = qtk[row0], t1 = qtk[row1];
#pragma unroll
    for (int jo = 0; jo < 8; jo++) {
        int col = (jo << 3) + ((lane & 3) << 1);
        if (t0 >= 0) {
            float vx = accO[jo][0] * f0, vy = accO[jo][1] * f0;
            size_t idx = ((size_t)(b * Tt + t0)) * Dd + (h << 6) + col;
            uint32_t hv = packbf(vx, vy);
            __nv_bfloat162 h2 = *(__nv_bfloat162*)&hv;
            uint32_t lv = packbf(vx - __bfloat162float(h2.x), vy - __bfloat162float(h2.y));
            *(uint32_t*)(g_Chi + idx) = hv;
            *(uint32_t*)(g_Clo + idx) = lv;
        }
        if (t1 >= 0) {
            float vx = accO[jo][2] * f1, vy = accO[jo][3] * f1;
            size_t idx = ((size_t)(b * Tt + t1)) * Dd + (h << 6) + col;
            uint32_t hv = packbf(vx, vy);
            __nv_bfloat162 h2 = *(__nv_bfloat162*)&hv;
            uint32_t lv = packbf(vx - __bfloat162float(h2.x), vy - __bfloat162float(h2.y));
            *(uint32_t*)(g_Chi + idx) = hv;
            *(uint32_t*)(g_Clo + idx) = lv;
        }
    }
}

// ---------------- launch: 2-group pipelined (9 nodes, 3 streams) -----------
extern "C" void kernel_launch(void* const* d_in, const int* in_sizes, int n_in,
                              void* d_out, int out_size) {
    const float* X    = (const float*)d_in[0];
    const float* Wc   = (const float*)d_in[1];
    const float* bc   = (const float*)d_in[2];
    const float* Win  = (const float*)d_in[3];
    const float* bin  = (const float*)d_in[4];
    const float* Wout = (const float*)d_in[5];
    const float* bout = (const float*)d_in[6];
    float* out = (float*)d_out;

    static cudaStream_t s2 = nullptr, st1 = nullptr;
    static cudaEvent_t eFork = nullptr, eRank = nullptr, eD1 = nullptr;
    if (s2 == nullptr) {
        cudaStreamCreateWithFlags(&s2,  cudaStreamNonBlocking);
        cudaStreamCreateWithFlags(&st1, cudaStreamNonBlocking);
        cudaEventCreateWithFlags(&eFork, cudaEventDisableTiming);
        cudaEventCreateWithFlags(&eRank, cudaEventDisableTiming);
        cudaEventCreateWithFlags(&eD1, cudaEventDisableTiming);
        cudaFuncSetAttribute(k_gemm1, cudaFuncAttributeMaxDynamicSharedMemorySize, GSM1);
    }

    cudaEventRecord(eFork, 0);
    cudaStreamWaitEvent(s2, eFork, 0);
    cudaStreamWaitEvent(st1, eFork, 0);

    // cluster assignment branch
    k_assign<<<(Bc * Tt) / 8, 256, 0, s2>>>(X, Wc, bc);
    k_rank<<<Bc, 1024, 0, s2>>>();
    cudaEventRecord(eRank, s2);

    // group 0 = batches {0,1} on main, group 1 = batches {2,3} on st1
    k_gemm0<<<dim3(12, 16), 256, GSM0, 0>>>(X, Win, bin, 0);
    k_gemm0<<<dim3(12, 16), 256, GSM0, st1>>>(X, Win, bin, 16);

    cudaStreamWaitEvent(0, eRank, 0);
    k_attn<<<2048, 128, 0, 0>>>(0);
    k_gemm1<<<dim3(4, 16), 256, GSM1, 0>>>(Wout, bout, out, 0);

    cudaStreamWaitEvent(st1, eRank, 0);
    k_attn<<<2048, 128, 0, st1>>>(2);
    k_gemm1<<<dim3(4, 16), 256, GSM1, st1>>>(Wout, bout, out, 16);
    cudaEventRecord(eD1, st1);

    cudaStreamWaitEvent(0, eD1, 0);
}